// round 16
// baseline (speedup 1.0000x reference)
#include <cuda_runtime.h>

// Problem constants (fixed shapes from the reference setup)
#define NB   16      // batch
#define NT   128     // time
#define NHWC 25088   // 56*56*8 floats per frame
#define NS4  6272    // NHWC / 4 (float4 strips per frame)
#define NC   8       // channels
#define KCH  4       // time chunks
#define TC   (NT / KCH)             // 32 frames per chunk
#define BT   224                    // block threads; NS4 = 28 * 224 exactly
#define NW   (BT / 32)              // 7 warps
#define NBLK_S (NS4 / BT)           // 28 blocks over the spatial strip
#define NBLKS  (NB * KCH * NBLK_S)  // 1792 total blocks

// Packed f32x2 helpers (sm_103a native packed fp32 pipe)
#define F2ADD(r, a, b) asm("add.rn.f32x2 %0, %1, %2;" : "=l"(r) : "l"(a), "l"(b))
#define F2UNPACK(lo, hi, v) asm("mov.b64 {%0, %1}, %2;" : "=f"(lo), "=f"(hi) : "l"(v))
#define ABS2MASK 0x7FFFFFFF7FFFFFFFULL
#define NEG2MASK 0x8000000080000000ULL

// Accumulators (no device allocation allowed -> __device__ globals).
// Zero at module load; the LAST block resets them every launch, so the
// zero-invariant holds across the correctness run and every graph replay.
__device__ double       g_act[NB * NC];
__device__ double       g_tot[NB * NC];
__device__ double       g_ttvb[NB];
__device__ unsigned int g_ctr;   // zero at load; last block resets to 0

__global__ __launch_bounds__(BT) void fused_kernel(const float4* __restrict__ x,
                                                   const int*   __restrict__ length,
                                                   const float* __restrict__ count,
                                                   float*       __restrict__ out) {
    const int s4    = blockIdx.x * BT + threadIdx.x;   // always < NS4
    const int chunk = blockIdx.y;
    const int b     = blockIdx.z;
    const int len   = __ldg(&length[b]);
    const int t0    = chunk * TC;
    const ulonglong2* base2 =
        (const ulonglong2*)(x + (size_t)b * NT * NS4) + s4;

    float ax, ay, az, aw;   // active sums (4 channels)
    float tx, ty, tz, tw;   // total sums
    float ttv;

    if (len >= t0 + TC) {
        // ---- FULL chunk: every frame active; active == total; no selects ----
        unsigned long long t01 = 0, t23 = 0, s01 = 0, s23 = 0;
        ulonglong2 p2;
        int ts = t0;
        if (t0 > 0) {
            p2 = __ldcs(&base2[(size_t)(t0 - 1) * NS4]);
        } else {
            p2 = __ldcs(&base2[0]);            // peel t=0 (no diff at t=0)
            F2ADD(t01, t01, p2.x);
            F2ADD(t23, t23, p2.y);
            ts = 1;
        }
        #pragma unroll 8
        for (int t = ts; t < t0 + TC; ++t) {
            ulonglong2 v2 = __ldcs(&base2[(size_t)t * NS4]);
            F2ADD(t01, t01, v2.x);
            F2ADD(t23, t23, v2.y);
            unsigned long long n0 = p2.x ^ NEG2MASK;   // -p (packed)
            unsigned long long n1 = p2.y ^ NEG2MASK;
            unsigned long long d0, d1;
            F2ADD(d0, v2.x, n0);                       // v - p
            F2ADD(d1, v2.y, n1);
            d0 &= ABS2MASK;                            // |v - p| (packed)
            d1 &= ABS2MASK;
            F2ADD(s01, s01, d0);
            F2ADD(s23, s23, d1);
            p2 = v2;
        }
        F2UNPACK(tx, ty, t01);
        F2UNPACK(tz, tw, t23);
        ax = tx; ay = ty; az = tz; aw = tw;
        float s0, s1, s2, s3;
        F2UNPACK(s0, s1, s01);
        F2UNPACK(s2, s3, s23);
        ttv = (s0 + s1) + (s2 + s3);
    } else if (len < t0) {
        // ---- BLANK chunk: no active frames, prev blank too -> ttv = 0 ----
        unsigned long long t01 = 0, t23 = 0;
        #pragma unroll 8
        for (int t = t0; t < t0 + TC; ++t) {
            ulonglong2 v2 = __ldcs(&base2[(size_t)t * NS4]);
            F2ADD(t01, t01, v2.x);
            F2ADD(t23, t23, v2.y);
        }
        F2UNPACK(tx, ty, t01);
        F2UNPACK(tz, tw, t23);
        ax = 0.f; ay = 0.f; az = 0.f; aw = 0.f;
        ttv = 0.f;
    } else {
        // ---- MIXED chunk (t0 <= len < t0+TC): general masked path ----
        const float4* base = (const float4*)base2;
        ax = ay = az = aw = 0.f;
        tx = ty = tz = tw = 0.f;
        ttv = 0.f;
        float px = 0.f, py = 0.f, pz = 0.f, pw = 0.f;
        if (t0 > 0 && (t0 - 1) < len) {
            float4 p = __ldcs(&base[(size_t)(t0 - 1) * NS4]);
            px = p.x; py = p.y; pz = p.z; pw = p.w;
        }
        #pragma unroll 8
        for (int t = t0; t < t0 + TC; ++t) {
            float4 v = __ldcs(&base[(size_t)t * NS4]);
            tx += v.x; ty += v.y; tz += v.z; tw += v.w;
            float cx, cy, cz, cw;
            if (t < len) {
                cx = v.x; cy = v.y; cz = v.z; cw = v.w;
                ax += v.x; ay += v.y; az += v.z; aw += v.w;
            } else {
                cx = 0.f; cy = 0.f; cz = 0.f; cw = 0.f;
            }
            if (t > 0) {
                ttv += fabsf(cx - px) + fabsf(cy - py) + fabsf(cz - pz) + fabsf(cw - pw);
            }
            px = cx; py = cy; pz = cz; pw = cw;
        }
    }

    // --- block reduction ---
    #pragma unroll
    for (int m = 16; m >= 1; m >>= 1)
        ttv += __shfl_xor_sync(0xffffffffu, ttv, m);
    // Parity-preserving reduce: even lanes hold channels 0-3, odd lanes 4-7
    #pragma unroll
    for (int m = 2; m <= 16; m <<= 1) {
        ax += __shfl_xor_sync(0xffffffffu, ax, m);
        ay += __shfl_xor_sync(0xffffffffu, ay, m);
        az += __shfl_xor_sync(0xffffffffu, az, m);
        aw += __shfl_xor_sync(0xffffffffu, aw, m);
        tx += __shfl_xor_sync(0xffffffffu, tx, m);
        ty += __shfl_xor_sync(0xffffffffu, ty, m);
        tz += __shfl_xor_sync(0xffffffffu, tz, m);
        tw += __shfl_xor_sync(0xffffffffu, tw, m);
    }

    __shared__ float sh_a[NW][NC];
    __shared__ float sh_t[NW][NC];
    __shared__ float sh_v[NW];
    const int w = threadIdx.x >> 5, lane = threadIdx.x & 31;
    if (lane == 0) {
        sh_a[w][0] = ax; sh_a[w][1] = ay; sh_a[w][2] = az; sh_a[w][3] = aw;
        sh_t[w][0] = tx; sh_t[w][1] = ty; sh_t[w][2] = tz; sh_t[w][3] = tw;
        sh_v[w] = ttv;
    } else if (lane == 1) {
        sh_a[w][4] = ax; sh_a[w][5] = ay; sh_a[w][6] = az; sh_a[w][7] = aw;
        sh_t[w][4] = tx; sh_t[w][5] = ty; sh_t[w][6] = tz; sh_t[w][7] = tw;
    }
    __syncthreads();

    // Per-(b,c) fp64 atomic accumulation: 17 REDGs per block, 112 ops/address.
    if (threadIdx.x < NC) {
        const int c = threadIdx.x;
        float sa = 0.f, st = 0.f;
        #pragma unroll
        for (int w2 = 0; w2 < NW; ++w2) { sa += sh_a[w2][c]; st += sh_t[w2][c]; }
        atomicAdd(&g_act[b * NC + c], (double)sa);
        atomicAdd(&g_tot[b * NC + c], (double)st);
    } else if (threadIdx.x == NC) {
        float s = 0.f;
        #pragma unroll
        for (int w2 = 0; w2 < NW; ++w2) s += sh_v[w2];
        atomicAdd(&g_ttvb[b], (double)s);
    }

    // --- last-block tail via acq_rel counter (no __threadfence stall) ---
    __syncthreads();
    __shared__ bool s_last;
    if (threadIdx.x == 0) {
        unsigned int old;
        asm volatile("atom.add.acq_rel.gpu.global.u32 %0, [%1], 1;"
                     : "=r"(old) : "l"(&g_ctr) : "memory");
        s_last = (old == NBLKS - 1);
    }
    __syncthreads();
    if (!s_last) return;

    // --- tail (one block, ~1 us): read 144 doubles, Huber, write, reset ---
    __shared__ float sh_fa[NB * NC];
    __shared__ float sh_ft[NB * NC];
    __shared__ float sh_ftv[NB];
    const int i = threadIdx.x;
    if (i == 0) g_ctr = 0;          // restore invariant for next replay
    if (i < NB * NC) {
        sh_fa[i] = (float)__ldcg(&g_act[i]);
        sh_ft[i] = (float)__ldcg(&g_tot[i]);
        g_act[i] = 0.0;             // reset accumulators for next replay
        g_tot[i] = 0.0;
    } else if (i < NB * NC + NB) {
        const int bb = i - NB * NC;
        sh_ftv[bb] = (float)__ldcg(&g_ttvb[bb]);
        g_ttvb[bb] = 0.0;
    }
    __syncthreads();

    if (i < NB) {
        const int bb = i;
        float tv = 0.f;
        #pragma unroll
        for (int k = 0; k < NB; ++k) tv += sh_ftv[k];
        float ah = 0.f, bh = 0.f;
        #pragma unroll
        for (int c = 0; c < NC; ++c) {
            const float aa = sh_fa[bb * NC + c];
            const float tt = sh_ft[bb * NC + c];
            float e  = aa - __ldg(&count[bb * NC + c]);
            float ae = fabsf(e);
            ah += (ae <= 1.f) ? 0.5f * e * e : (ae - 0.5f);
            float eb  = tt - aa;
            float aeb = fabsf(eb);
            bh += (aeb <= 1.f) ? 0.5f * eb * eb : (aeb - 0.5f);
        }
        out[bb] = ah * (1.f / NC) + bh * (1.f / NC) + tv * 0.1f;
    }
}

extern "C" void kernel_launch(void* const* d_in, const int* in_sizes, int n_in,
                              void* d_out, int out_size) {
    const float* cam    = (const float*)d_in[0];
    const float* count  = (const float*)d_in[1];
    const int*   length = (const int*)d_in[2];
    float*       out    = (float*)d_out;

    dim3 grid(NBLK_S, KCH, NB);   // 28 x 4 x 16 = 1792 blocks
    fused_kernel<<<grid, BT>>>((const float4*)cam, length, count, out);
}